// round 10
// baseline (speedup 1.0000x reference)
#include <cuda_runtime.h>
#include <math.h>
#include <stddef.h>

// Problem constants
#define NN    4096      // nodes
#define TT    16        // timesteps / out features
#define FF    4         // node features
#define HIDC  64        // hidden per head
#define NH    4         // heads
#define NCHUNK 512
#define CHSZ   8        // NN / NCHUNK
#define CHLOG  3
#define SCAN_G 8

// ---------------------------------------------------------------------------
// Scratch (static device global)
// ---------------------------------------------------------------------------
struct Scratch {
    // layer 1
    float  Wh[NH * NN * HIDC];
    float  s1[NH * NN];
    float  s2[NH * NN];
    float  s2s[NH * NN];
    int    perm[NH * NN];
    float  A[NH * NN];                 // exp(s2_sorted)
    float  B[NH * NN];                 // exp(0.01*s2_sorted)
    float  csA[NH * NCHUNK * HIDC];    // scanned: exclusive suffix per chunk
    float  csB[NH * NCHUNK * HIDC];    // scanned: exclusive prefix per chunk
    double sufAsc[NH * (NN + 1)];
    double preBsc[NH * (NN + 1)];
    float  hcat[NN * NH * HIDC];
    // layer 2
    float  Wh2[NN * TT];
    float  s1o[NN], s2o[NN], s2so[NN];
    int    permo[NN];
    float  Ao[NN], Bo[NN];
    float  csA2[NCHUNK * TT], csB2[NCHUNK * TT];
    double sufA2sc[NN + 1], preB2sc[NN + 1];
};
__device__ Scratch S;

// ---------------------------------------------------------------------------
// Kernel 1: fused transpose(x) -> h, Wh = h @ W[head], s1/s2 dots
// grid (NN/64, NH), block 256
// ---------------------------------------------------------------------------
__global__ void k_gemm1(const float* __restrict__ x,
                        const float* __restrict__ W,
                        const float* __restrict__ a1,
                        const float* __restrict__ a2)
{
    __shared__ float sW[64 * 65];
    __shared__ float sh[64 * 65];

    const int head = blockIdx.y;
    const int n0   = blockIdx.x * 64;
    const int t    = threadIdx.x;

    const float* Wp = W + head * 64 * 64;
    for (int idx = t; idx < 4096; idx += 256)
        sW[(idx >> 6) * 65 + (idx & 63)] = Wp[idx];

    {
        const int dn = t >> 2, f = t & 3;
        #pragma unroll
        for (int tt = 0; tt < TT; tt++)
            sh[dn * 65 + tt * 4 + f] = x[(size_t)tt * NN * FF + (size_t)(n0 + dn) * FF + f];
    }
    __syncthreads();

    const int tc = t & 15, tr = t >> 4;
    float acc[4][4];
    #pragma unroll
    for (int i = 0; i < 4; i++)
        #pragma unroll
        for (int j = 0; j < 4; j++) acc[i][j] = 0.f;

    for (int k = 0; k < 64; k++) {
        float av[4], bv[4];
        #pragma unroll
        for (int i = 0; i < 4; i++) av[i] = sh[(tr + 16 * i) * 65 + k];
        #pragma unroll
        for (int j = 0; j < 4; j++) bv[j] = sW[k * 65 + tc + 16 * j];
        #pragma unroll
        for (int i = 0; i < 4; i++)
            #pragma unroll
            for (int j = 0; j < 4; j++) acc[i][j] = fmaf(av[i], bv[j], acc[i][j]);
    }
    __syncthreads();

    float* __restrict__ WhG = S.Wh;
    #pragma unroll
    for (int i = 0; i < 4; i++) {
        const int r = tr + 16 * i;
        #pragma unroll
        for (int j = 0; j < 4; j++) {
            const int c = tc + 16 * j;
            sW[r * 65 + c] = acc[i][j];
            WhG[((size_t)head * NN + (n0 + r)) * HIDC + c] = acc[i][j];
        }
    }
    __syncthreads();

    if (t < 64) {
        const int r = t;
        const float* ap1 = a1 + head * HIDC;
        const float* ap2 = a2 + head * HIDC;
        float v1 = 0.f, v2 = 0.f;
        #pragma unroll
        for (int c = 0; c < 64; c++) {
            const float w = sW[r * 65 + c];
            v1 = fmaf(w, ap1[c], v1);
            v2 = fmaf(w, ap2[c], v2);
        }
        S.s1[head * NN + n0 + r] = v1;
        S.s2[head * NN + n0 + r] = v2;
    }
}

// ---------------------------------------------------------------------------
// Kernel 2: hcat @ W_out + s1o/s2o.  grid 256, block 256
// ---------------------------------------------------------------------------
__global__ void k_gemm2(const float* __restrict__ Wo,
                        const float* __restrict__ a1,
                        const float* __restrict__ a2)
{
    __shared__ float sW[256 * 17];
    __shared__ float sh2[16 * 257];
    __shared__ float sAcc[16 * 17];

    const float* __restrict__ hcat = S.hcat;
    const int row0 = blockIdx.x * 16;
    const int t    = threadIdx.x;

    for (int idx = t; idx < 4096; idx += 256)
        sW[(idx >> 4) * 17 + (idx & 15)] = Wo[idx];
    #pragma unroll
    for (int r = 0; r < 16; r++)
        sh2[r * 257 + t] = hcat[(size_t)(row0 + r) * 256 + t];
    __syncthreads();

    const int tc = t & 15, tr = t >> 4;
    float acc = 0.f;
    #pragma unroll 8
    for (int k = 0; k < 256; k++)
        acc = fmaf(sh2[tr * 257 + k], sW[k * 17 + tc], acc);

    S.Wh2[(row0 + tr) * TT + tc] = acc;
    sAcc[tr * 17 + tc] = acc;
    __syncthreads();

    if (t < 16) {
        const int r = t;
        float v1 = 0.f, v2 = 0.f;
        #pragma unroll
        for (int c = 0; c < 16; c++) {
            const float w = sAcc[r * 17 + c];
            v1 = fmaf(w, a1[c], v1);
            v2 = fmaf(w, a2[c], v2);
        }
        S.s1o[row0 + r] = v1;
        S.s2o[row0 + r] = v2;
    }
}

// ---------------------------------------------------------------------------
// Kernel 3: bitonic sort (register/shuffle) + exp weights + fused fp64 scans
// 1 block of 1024 per head.
// ---------------------------------------------------------------------------
template<int L>
__global__ void k_sortscan()
{
    const float* __restrict__ s2  = (L == 0) ? S.s2  : S.s2o;
    float*       __restrict__ s2s = (L == 0) ? S.s2s : S.s2so;
    int*         __restrict__ perm= (L == 0) ? S.perm: S.permo;
    float*       __restrict__ A   = (L == 0) ? S.A   : S.Ao;
    float*       __restrict__ B   = (L == 0) ? S.B   : S.Bo;
    double*      __restrict__ sufAsc = ((L == 0) ? S.sufAsc : S.sufA2sc) + blockIdx.x * (NN + 1);
    double*      __restrict__ preBsc = ((L == 0) ? S.preBsc : S.preB2sc) + blockIdx.x * (NN + 1);

    __shared__ float key[NN];
    __shared__ int   sidx[NN];          // reused as double seg[2048] later

    const int base = blockIdx.x * NN;
    const int t    = threadIdx.x;
    const int lane = t & 31;

    float k0[4]; int x0[4];
    #pragma unroll
    for (int m = 0; m < 4; m++) {
        const int i = t + m * 1024;
        k0[m] = s2[base + i];
        x0[m] = i;
    }

    // stages k=2..32 entirely in registers (partner always in-warp)
    #pragma unroll
    for (int k = 2; k <= 32; k <<= 1) {
        #pragma unroll
        for (int j = k >> 1; j >= 1; j >>= 1) {
            #pragma unroll
            for (int m = 0; m < 4; m++) {
                const int i = t + m * 1024;
                const bool up = ((i & k) == 0);
                const float ok = __shfl_xor_sync(0xffffffffu, k0[m], j);
                const int   oi = __shfl_xor_sync(0xffffffffu, x0[m], j);
                const bool lower = ((lane & j) == 0);
                const bool wantMin = (lower == up);
                const bool take = wantMin ? (ok < k0[m]) : (ok > k0[m]);
                if (take) { k0[m] = ok; x0[m] = oi; }
            }
        }
    }
    #pragma unroll
    for (int m = 0; m < 4; m++) {
        const int i = t + m * 1024;
        key[i] = k0[m]; sidx[i] = x0[m];
    }
    __syncthreads();

    // stages k=64..4096: smem passes down to j=32, then in-warp shuffle tail
    for (int k = 64; k <= NN; k <<= 1) {
        for (int j = k >> 1; j >= 32; j >>= 1) {
            #pragma unroll
            for (int m = 0; m < 4; m++) {
                const int i = t + m * 1024;
                const int ixj = i ^ j;
                if (ixj > i) {
                    const bool up = ((i & k) == 0);
                    const float a = key[i], b = key[ixj];
                    if ((a > b) == up) {
                        key[i] = b; key[ixj] = a;
                        const int tmp = sidx[i]; sidx[i] = sidx[ixj]; sidx[ixj] = tmp;
                    }
                }
            }
            __syncthreads();
        }
        #pragma unroll
        for (int m = 0; m < 4; m++) {
            const int i = t + m * 1024;
            k0[m] = key[i]; x0[m] = sidx[i];
        }
        #pragma unroll
        for (int j = 16; j >= 1; j >>= 1) {
            #pragma unroll
            for (int m = 0; m < 4; m++) {
                const int i = t + m * 1024;
                const bool up = ((i & k) == 0);
                const float ok = __shfl_xor_sync(0xffffffffu, k0[m], j);
                const int   oi = __shfl_xor_sync(0xffffffffu, x0[m], j);
                const bool lower = ((lane & j) == 0);
                const bool wantMin = (lower == up);
                const bool take = wantMin ? (ok < k0[m]) : (ok > k0[m]);
                if (take) { k0[m] = ok; x0[m] = oi; }
            }
        }
        #pragma unroll
        for (int m = 0; m < 4; m++) {
            const int i = t + m * 1024;
            key[i] = k0[m]; sidx[i] = x0[m];
        }
        __syncthreads();
    }

    // write sorted keys / perm / exp weights from registers
    #pragma unroll
    for (int m = 0; m < 4; m++) {
        const int i = t + m * 1024;
        const float v = k0[m];
        s2s[base + i]  = v;
        perm[base + i] = x0[m];
        A[base + i]    = expf(v);
        B[base + i]    = expf(0.01f * v);
    }
    __syncthreads();

    // fused scalar scans (fp64): thread t owns positions 4t..4t+3
    double* seg = (double*)sidx;     // 2048 doubles
    float av[4], bv[4];
    double la = 0.0, lb = 0.0;
    #pragma unroll
    for (int e = 0; e < 4; e++) {
        const float v = key[4 * t + e];
        av[e] = expf(v); bv[e] = expf(0.01f * v);
        la += (double)av[e]; lb += (double)bv[e];
    }
    seg[t] = la; seg[1024 + t] = lb;
    __syncthreads();

    for (int d = 1; d < 1024; d <<= 1) {
        double va = 0.0, vb = 0.0;
        if (t >= d) { va = seg[t - d]; vb = seg[1024 + t - d]; }
        __syncthreads();
        seg[t] += va; seg[1024 + t] += vb;
        __syncthreads();
    }

    const double exA = seg[t] - la;
    const double exB = seg[1024 + t] - lb;
    const double totA = seg[1023];
    const double totB = seg[2047];

    double runB = exB, runA = exA;
    #pragma unroll
    for (int e = 0; e < 4; e++) {
        const int p = 4 * t + e;
        preBsc[p] = runB;        runB += (double)bv[e];
        sufAsc[p] = totA - runA; runA += (double)av[e];
    }
    if (t == 1023) { preBsc[NN] = totB; sufAsc[NN] = 0.0; }
}

// ---------------------------------------------------------------------------
// Kernel 4 (fused): chunk sums + in-block scan, no intermediate global trip.
// Block = (head, group of 8 channels), 256 threads, smem-resident cs tiles.
// Phase 1: compute A/B-weighted chunk sums for 8 channels x 512 chunks.
// Phase 2: warp w scans channel w (B: exclusive prefix, A: exclusive suffix)
//          via 16 independent pipelined warp scans + register combine.
// Phase 3: write scanned values to csA/csB.
// ---------------------------------------------------------------------------
template<int C, int L>
__global__ void k_sumscan()
{
    __shared__ float sA[NCHUNK * 9];   // [q][9]: stride 9 coprime to 32
    __shared__ float sB[NCHUNK * 9];

    const int head = blockIdx.x;
    const int c0   = blockIdx.y * SCAN_G;
    const float* __restrict__ Wh   = ((L == 0) ? S.Wh   : S.Wh2)  + (size_t)head * NN * C;
    const int*   __restrict__ perm = ((L == 0) ? S.perm : S.permo) + head * NN;
    const float* __restrict__ A    = ((L == 0) ? S.A    : S.Ao)    + head * NN;
    const float* __restrict__ B    = ((L == 0) ? S.B    : S.Bo)    + head * NN;
    float*       __restrict__ csA  = ((L == 0) ? S.csA  : S.csA2)  + (size_t)head * NCHUNK * C;
    float*       __restrict__ csB  = ((L == 0) ? S.csB  : S.csB2)  + (size_t)head * NCHUNK * C;

    const int t    = threadIdx.x;
    const int lane = t & 31;
    const int w    = t >> 5;           // warp id = local channel

    // Phase 1: chunk sums. thread -> (q = t/8 + 32*i, cl = t%8)
    {
        const int cl = t & 7;
        const int qb = t >> 3;
        #pragma unroll
        for (int i = 0; i < NCHUNK / 32; i++) {
            const int q  = qb + 32 * i;
            const int p0 = q * CHSZ;
            float sa = 0.f, sb = 0.f;
            #pragma unroll
            for (int e = 0; e < CHSZ; e++) {
                const int p = p0 + e;
                const float wv = Wh[(size_t)perm[p] * C + c0 + cl];
                sa = fmaf(A[p], wv, sa);
                sb = fmaf(B[p], wv, sb);
            }
            sA[q * 9 + cl] = sa;
            sB[q * 9 + cl] = sb;
        }
    }
    __syncthreads();

    // Phase 2: scans. warp w owns channel w.
    constexpr int R = NCHUNK / 32;     // 16 rounds per lane
    {
        // B: exclusive prefix
        float vals[R], inc[R];
        #pragma unroll
        for (int i = 0; i < R; i++) {
            vals[i] = sB[(lane + 32 * i) * 9 + w];
            inc[i]  = vals[i];
        }
        #pragma unroll
        for (int d = 1; d < 32; d <<= 1) {
            #pragma unroll
            for (int i = 0; i < R; i++) {
                const float tv = __shfl_up_sync(0xffffffffu, inc[i], d);
                if (lane >= d) inc[i] += tv;
            }
        }
        float tot[R];
        #pragma unroll
        for (int i = 0; i < R; i++) tot[i] = __shfl_sync(0xffffffffu, inc[i], 31);
        float run = 0.f;
        #pragma unroll
        for (int i = 0; i < R; i++) {
            sB[(lane + 32 * i) * 9 + w] = run + (inc[i] - vals[i]);
            run += tot[i];
        }
    }
    {
        // A: exclusive suffix
        float vals[R], inc[R];
        #pragma unroll
        for (int i = 0; i < R; i++) {
            vals[i] = sA[(lane + 32 * i) * 9 + w];
            inc[i]  = vals[i];
        }
        #pragma unroll
        for (int d = 1; d < 32; d <<= 1) {
            #pragma unroll
            for (int i = 0; i < R; i++) {
                const float tv = __shfl_up_sync(0xffffffffu, inc[i], d);
                if (lane >= d) inc[i] += tv;
            }
        }
        float tot[R];
        #pragma unroll
        for (int i = 0; i < R; i++) tot[i] = __shfl_sync(0xffffffffu, inc[i], 31);
        float run = 0.f;
        #pragma unroll
        for (int i = R - 1; i >= 0; i--) {
            sA[(lane + 32 * i) * 9 + w] = run + (tot[i] - inc[i]);
            run += tot[i];
        }
    }
    __syncthreads();

    // Phase 3: write out scanned values
    for (int idx = t; idx < NCHUNK * SCAN_G; idx += 256) {
        const int q  = idx >> 3;
        const int cl = idx & 7;
        csA[q * C + c0 + cl] = sA[q * 9 + cl];
        csB[q * C + c0 + cl] = sB[q * 9 + cl];
    }
}

// ---------------------------------------------------------------------------
// Kernel 5: per-row combine; row-level scalars computed once per row and
// shared via smem.  block 256 = IPB rows x C channels.
// ---------------------------------------------------------------------------
template<int C, bool DO_ELU, int L>
__global__ void k_combine(float* __restrict__ extOut, int rowStride)
{
    constexpr int IPB = 256 / C;
    __shared__ int    skk[IPB];
    __shared__ float  sEa[IPB], sEb[IPB], sWii[IPB];
    __shared__ double sRd[IPB];

    const int head = blockIdx.y;
    const float*  __restrict__ s1     = ((L == 0) ? S.s1     : S.s1o)  + head * NN;
    const float*  __restrict__ s2     = ((L == 0) ? S.s2     : S.s2o)  + head * NN;
    const float*  __restrict__ s2s    = ((L == 0) ? S.s2s    : S.s2so) + head * NN;
    const int*    __restrict__ perm   = ((L == 0) ? S.perm   : S.permo) + head * NN;
    const float*  __restrict__ A      = ((L == 0) ? S.A      : S.Ao)   + head * NN;
    const float*  __restrict__ B      = ((L == 0) ? S.B      : S.Bo)   + head * NN;
    const float*  __restrict__ Wh     = ((L == 0) ? S.Wh     : S.Wh2)  + (size_t)head * NN * C;
    const float*  __restrict__ csAs   = ((L == 0) ? S.csA    : S.csA2) + (size_t)head * NCHUNK * C;
    const float*  __restrict__ csBs   = ((L == 0) ? S.csB    : S.csB2) + (size_t)head * NCHUNK * C;
    const double* __restrict__ sufAsc = ((L == 0) ? S.sufAsc : S.sufA2sc) + head * (NN + 1);
    const double* __restrict__ preBsc = ((L == 0) ? S.preBsc : S.preB2sc) + head * (NN + 1);
    float* __restrict__ out = (L == 0) ? S.hcat : extOut;

    const int r = threadIdx.x / C;
    const int i = blockIdx.x * IPB + r;
    const int c = threadIdx.x % C;

    if (c == 0) {
        const float s1v = s1[i];
        const float ea  = expf(s1v);
        const float eb  = expf(0.01f * s1v);
        const float target = -s1v;
        int lo = 0, hi = NN;
        while (lo < hi) {
            const int mid = (lo + hi) >> 1;
            if (s2s[mid] < target) lo = mid + 1; else hi = mid;
        }
        const float tii = s1v + s2[i];
        const float wii = expf(tii >= 0.f ? tii : 0.01f * tii);
        const double denom = (double)ea * sufAsc[lo] + (double)eb * preBsc[lo] - (double)wii;
        skk[r] = lo;  sEa[r] = ea;  sEb[r] = eb;  sWii[r] = wii;
        sRd[r] = 1.0 / denom;
    }
    __syncthreads();

    const int   k   = skk[r];
    const float ea  = sEa[r];
    const float eb  = sEb[r];
    const float wii = sWii[r];
    const double rd = sRd[r];
    const int q = min(k >> CHLOG, NCHUNK - 1);

    float accA = csAs[q * C + c];     // sum over chunks > q (A-weighted)
    float accB = csBs[q * C + c];     // sum over chunks < q (B-weighted)

    const int p0 = q << CHLOG;
    #pragma unroll
    for (int e = 0; e < CHSZ; e++) {
        const int p = p0 + e;
        const float w = Wh[(size_t)perm[p] * C + c];
        if (p >= k) accA = fmaf(A[p], w, accA);
        else        accB = fmaf(B[p], w, accB);
    }

    const float num = ea * accA + eb * accB - wii * Wh[(size_t)i * C + c];
    float v = (float)((double)num * rd);
    if (DO_ELU) v = (v > 0.f) ? v : expm1f(v);

    out[(size_t)i * rowStride + head * C + c] = v;
}

// ---------------------------------------------------------------------------
// launch — kernel launches only (8 launches)
// ---------------------------------------------------------------------------
extern "C" void kernel_launch(void* const* d_in, const int* in_sizes, int n_in,
                              void* d_out, int out_size)
{
    const float* x       = (const float*)d_in[0];
    const float* W_heads = (const float*)d_in[3];
    const float* a1h     = (const float*)d_in[4];
    const float* a2h     = (const float*)d_in[5];
    const float* W_out   = (const float*)d_in[6];
    const float* a1o     = (const float*)d_in[7];
    const float* a2o     = (const float*)d_in[8];
    float* out = (float*)d_out;

    // ---- layer 1 (4 heads) ----
    k_gemm1<<<dim3(NN / 64, NH), 256>>>(x, W_heads, a1h, a2h);
    k_sortscan<0><<<NH, 1024>>>();
    k_sumscan<HIDC, 0><<<dim3(NH, HIDC / SCAN_G), 256>>>();
    k_combine<HIDC, true, 0><<<dim3(NN / 4, NH), 256>>>(nullptr, NH * HIDC);

    // ---- layer 2 (output) ----
    k_gemm2<<<NN / 16, 256>>>(W_out, a1o, a2o);
    k_sortscan<1><<<1, 1024>>>();
    k_sumscan<TT, 1><<<dim3(1, TT / SCAN_G), 256>>>();
    k_combine<TT, false, 1><<<dim3(NN / 16, 1), 256>>>(out, TT);
}

// round 11
// speedup vs baseline: 1.2010x; 1.2010x over previous
#include <cuda_runtime.h>
#include <math.h>
#include <stddef.h>

// Problem constants
#define NN    4096      // nodes
#define TT    16        // timesteps / out features
#define FF    4         // node features
#define HIDC  64        // hidden per head
#define NH    4         // heads
#define NCHUNK 512
#define CHSZ   8        // NN / NCHUNK
#define CHLOG  3
#define SCAN_G 8

// ---------------------------------------------------------------------------
// Scratch (static device global)
// ---------------------------------------------------------------------------
struct Scratch {
    // layer 1
    float  Wh[NH * NN * HIDC];
    float  s1[NH * NN];
    float  s2[NH * NN];
    float  s2s[NH * NN];
    int    perm[NH * NN];
    float  A[NH * NN];                 // exp(s2_sorted)
    float  B[NH * NN];                 // exp(0.01*s2_sorted)
    float  csA[NH * NCHUNK * HIDC];    // chunk sums -> exclusive suffix (scanned)
    float  csB[NH * NCHUNK * HIDC];    // chunk sums -> exclusive prefix (scanned)
    double sufAsc[NH * (NN + 1)];
    double preBsc[NH * (NN + 1)];
    float  hcat[NN * NH * HIDC];
    // layer 2
    float  Wh2[NN * TT];
    float  s1o[NN], s2o[NN], s2so[NN];
    int    permo[NN];
    float  Ao[NN], Bo[NN];
    float  csA2[NCHUNK * TT], csB2[NCHUNK * TT];
    double sufA2sc[NN + 1], preB2sc[NN + 1];
};
__device__ Scratch S;

// ---------------------------------------------------------------------------
// Kernel 1: fused transpose(x) -> h, Wh = h @ W[head], s1/s2 dots
// grid (NN/64, NH), block 256
// ---------------------------------------------------------------------------
__global__ void k_gemm1(const float* __restrict__ x,
                        const float* __restrict__ W,
                        const float* __restrict__ a1,
                        const float* __restrict__ a2)
{
    __shared__ float sW[64 * 65];
    __shared__ float sh[64 * 65];

    const int head = blockIdx.y;
    const int n0   = blockIdx.x * 64;
    const int t    = threadIdx.x;

    const float* Wp = W + head * 64 * 64;
    for (int idx = t; idx < 4096; idx += 256)
        sW[(idx >> 6) * 65 + (idx & 63)] = Wp[idx];

    {
        const int dn = t >> 2, f = t & 3;
        #pragma unroll
        for (int tt = 0; tt < TT; tt++)
            sh[dn * 65 + tt * 4 + f] = x[(size_t)tt * NN * FF + (size_t)(n0 + dn) * FF + f];
    }
    __syncthreads();

    const int tc = t & 15, tr = t >> 4;
    float acc[4][4];
    #pragma unroll
    for (int i = 0; i < 4; i++)
        #pragma unroll
        for (int j = 0; j < 4; j++) acc[i][j] = 0.f;

    for (int k = 0; k < 64; k++) {
        float av[4], bv[4];
        #pragma unroll
        for (int i = 0; i < 4; i++) av[i] = sh[(tr + 16 * i) * 65 + k];
        #pragma unroll
        for (int j = 0; j < 4; j++) bv[j] = sW[k * 65 + tc + 16 * j];
        #pragma unroll
        for (int i = 0; i < 4; i++)
            #pragma unroll
            for (int j = 0; j < 4; j++) acc[i][j] = fmaf(av[i], bv[j], acc[i][j]);
    }
    __syncthreads();

    float* __restrict__ WhG = S.Wh;
    #pragma unroll
    for (int i = 0; i < 4; i++) {
        const int r = tr + 16 * i;
        #pragma unroll
        for (int j = 0; j < 4; j++) {
            const int c = tc + 16 * j;
            sW[r * 65 + c] = acc[i][j];
            WhG[((size_t)head * NN + (n0 + r)) * HIDC + c] = acc[i][j];
        }
    }
    __syncthreads();

    if (t < 64) {
        const int r = t;
        const float* ap1 = a1 + head * HIDC;
        const float* ap2 = a2 + head * HIDC;
        float v1 = 0.f, v2 = 0.f;
        #pragma unroll
        for (int c = 0; c < 64; c++) {
            const float w = sW[r * 65 + c];
            v1 = fmaf(w, ap1[c], v1);
            v2 = fmaf(w, ap2[c], v2);
        }
        S.s1[head * NN + n0 + r] = v1;
        S.s2[head * NN + n0 + r] = v2;
    }
}

// ---------------------------------------------------------------------------
// Kernel 2: hcat @ W_out + s1o/s2o.  grid 256, block 256
// ---------------------------------------------------------------------------
__global__ void k_gemm2(const float* __restrict__ Wo,
                        const float* __restrict__ a1,
                        const float* __restrict__ a2)
{
    __shared__ float sW[256 * 17];
    __shared__ float sh2[16 * 257];
    __shared__ float sAcc[16 * 17];

    const float* __restrict__ hcat = S.hcat;
    const int row0 = blockIdx.x * 16;
    const int t    = threadIdx.x;

    for (int idx = t; idx < 4096; idx += 256)
        sW[(idx >> 4) * 17 + (idx & 15)] = Wo[idx];
    #pragma unroll
    for (int r = 0; r < 16; r++)
        sh2[r * 257 + t] = hcat[(size_t)(row0 + r) * 256 + t];
    __syncthreads();

    const int tc = t & 15, tr = t >> 4;
    float acc = 0.f;
    #pragma unroll 8
    for (int k = 0; k < 256; k++)
        acc = fmaf(sh2[tr * 257 + k], sW[k * 17 + tc], acc);

    S.Wh2[(row0 + tr) * TT + tc] = acc;
    sAcc[tr * 17 + tc] = acc;
    __syncthreads();

    if (t < 16) {
        const int r = t;
        float v1 = 0.f, v2 = 0.f;
        #pragma unroll
        for (int c = 0; c < 16; c++) {
            const float w = sAcc[r * 17 + c];
            v1 = fmaf(w, a1[c], v1);
            v2 = fmaf(w, a2[c], v2);
        }
        S.s1o[row0 + r] = v1;
        S.s2o[row0 + r] = v2;
    }
}

// ---------------------------------------------------------------------------
// Kernel 3: bitonic sort (register/shuffle) + exp weights + fused fp64 scans
// 1 block of 1024 per head.
// ---------------------------------------------------------------------------
template<int L>
__global__ void k_sortscan()
{
    const float* __restrict__ s2  = (L == 0) ? S.s2  : S.s2o;
    float*       __restrict__ s2s = (L == 0) ? S.s2s : S.s2so;
    int*         __restrict__ perm= (L == 0) ? S.perm: S.permo;
    float*       __restrict__ A   = (L == 0) ? S.A   : S.Ao;
    float*       __restrict__ B   = (L == 0) ? S.B   : S.Bo;
    double*      __restrict__ sufAsc = ((L == 0) ? S.sufAsc : S.sufA2sc) + blockIdx.x * (NN + 1);
    double*      __restrict__ preBsc = ((L == 0) ? S.preBsc : S.preB2sc) + blockIdx.x * (NN + 1);

    __shared__ float key[NN];
    __shared__ int   sidx[NN];          // reused as double seg[2048] later

    const int base = blockIdx.x * NN;
    const int t    = threadIdx.x;
    const int lane = t & 31;

    float k0[4]; int x0[4];
    #pragma unroll
    for (int m = 0; m < 4; m++) {
        const int i = t + m * 1024;
        k0[m] = s2[base + i];
        x0[m] = i;
    }

    // stages k=2..32 entirely in registers (partner always in-warp)
    #pragma unroll
    for (int k = 2; k <= 32; k <<= 1) {
        #pragma unroll
        for (int j = k >> 1; j >= 1; j >>= 1) {
            #pragma unroll
            for (int m = 0; m < 4; m++) {
                const int i = t + m * 1024;
                const bool up = ((i & k) == 0);
                const float ok = __shfl_xor_sync(0xffffffffu, k0[m], j);
                const int   oi = __shfl_xor_sync(0xffffffffu, x0[m], j);
                const bool lower = ((lane & j) == 0);
                const bool wantMin = (lower == up);
                const bool take = wantMin ? (ok < k0[m]) : (ok > k0[m]);
                if (take) { k0[m] = ok; x0[m] = oi; }
            }
        }
    }
    #pragma unroll
    for (int m = 0; m < 4; m++) {
        const int i = t + m * 1024;
        key[i] = k0[m]; sidx[i] = x0[m];
    }
    __syncthreads();

    // stages k=64..4096: smem passes down to j=32, then in-warp shuffle tail
    for (int k = 64; k <= NN; k <<= 1) {
        for (int j = k >> 1; j >= 32; j >>= 1) {
            #pragma unroll
            for (int m = 0; m < 4; m++) {
                const int i = t + m * 1024;
                const int ixj = i ^ j;
                if (ixj > i) {
                    const bool up = ((i & k) == 0);
                    const float a = key[i], b = key[ixj];
                    if ((a > b) == up) {
                        key[i] = b; key[ixj] = a;
                        const int tmp = sidx[i]; sidx[i] = sidx[ixj]; sidx[ixj] = tmp;
                    }
                }
            }
            __syncthreads();
        }
        #pragma unroll
        for (int m = 0; m < 4; m++) {
            const int i = t + m * 1024;
            k0[m] = key[i]; x0[m] = sidx[i];
        }
        #pragma unroll
        for (int j = 16; j >= 1; j >>= 1) {
            #pragma unroll
            for (int m = 0; m < 4; m++) {
                const int i = t + m * 1024;
                const bool up = ((i & k) == 0);
                const float ok = __shfl_xor_sync(0xffffffffu, k0[m], j);
                const int   oi = __shfl_xor_sync(0xffffffffu, x0[m], j);
                const bool lower = ((lane & j) == 0);
                const bool wantMin = (lower == up);
                const bool take = wantMin ? (ok < k0[m]) : (ok > k0[m]);
                if (take) { k0[m] = ok; x0[m] = oi; }
            }
        }
        #pragma unroll
        for (int m = 0; m < 4; m++) {
            const int i = t + m * 1024;
            key[i] = k0[m]; sidx[i] = x0[m];
        }
        __syncthreads();
    }

    // write sorted keys / perm / exp weights from registers
    #pragma unroll
    for (int m = 0; m < 4; m++) {
        const int i = t + m * 1024;
        const float v = k0[m];
        s2s[base + i]  = v;
        perm[base + i] = x0[m];
        A[base + i]    = expf(v);
        B[base + i]    = expf(0.01f * v);
    }
    __syncthreads();

    // fused scalar scans (fp64): thread t owns positions 4t..4t+3
    double* seg = (double*)sidx;     // 2048 doubles
    float av[4], bv[4];
    double la = 0.0, lb = 0.0;
    #pragma unroll
    for (int e = 0; e < 4; e++) {
        const float v = key[4 * t + e];
        av[e] = expf(v); bv[e] = expf(0.01f * v);
        la += (double)av[e]; lb += (double)bv[e];
    }
    seg[t] = la; seg[1024 + t] = lb;
    __syncthreads();

    for (int d = 1; d < 1024; d <<= 1) {
        double va = 0.0, vb = 0.0;
        if (t >= d) { va = seg[t - d]; vb = seg[1024 + t - d]; }
        __syncthreads();
        seg[t] += va; seg[1024 + t] += vb;
        __syncthreads();
    }

    const double exA = seg[t] - la;
    const double exB = seg[1024 + t] - lb;
    const double totA = seg[1023];
    const double totB = seg[2047];

    double runB = exB, runA = exA;
    #pragma unroll
    for (int e = 0; e < 4; e++) {
        const int p = 4 * t + e;
        preBsc[p] = runB;        runB += (double)bv[e];
        sufAsc[p] = totA - runA; runA += (double)av[e];
    }
    if (t == 1023) { preBsc[NN] = totB; sufAsc[NN] = 0.0; }
}

// ---------------------------------------------------------------------------
// Kernel 4: per-chunk fp32 column sums of A*Wh[perm] and B*Wh[perm]
// ---------------------------------------------------------------------------
template<int C, int CPB, int L>
__global__ void k_chunksum()
{
    const int head = blockIdx.x;
    const float* __restrict__ Wh   = ((L == 0) ? S.Wh   : S.Wh2) + (size_t)head * NN * C;
    const int*   __restrict__ perm = ((L == 0) ? S.perm : S.permo) + head * NN;
    const float* __restrict__ A    = ((L == 0) ? S.A    : S.Ao)   + head * NN;
    const float* __restrict__ B    = ((L == 0) ? S.B    : S.Bo)   + head * NN;
    float*       __restrict__ csA  = ((L == 0) ? S.csA  : S.csA2) + (size_t)head * NCHUNK * C;
    float*       __restrict__ csB  = ((L == 0) ? S.csB  : S.csB2) + (size_t)head * NCHUNK * C;

    const int c = threadIdx.x % C;
    const int q = blockIdx.y * CPB + threadIdx.x / C;
    const int p0 = q * CHSZ;
    float sa = 0.f, sb = 0.f;
    #pragma unroll
    for (int e = 0; e < CHSZ; e++) {
        const int p = p0 + e;
        const float w = Wh[(size_t)perm[p] * C + c];
        sa = fmaf(A[p], w, sa);
        sb = fmaf(B[p], w, sb);
    }
    csA[q * C + c] = sa;
    csB[q * C + c] = sb;
}

// ---------------------------------------------------------------------------
// Kernel 5: scan of chunk sums — independent pipelined warp scans.
// blockIdx.z = 0 -> csB exclusive prefix; 1 -> csA exclusive suffix.
// ---------------------------------------------------------------------------
template<int C, int L>
__global__ void k_chunkscan()
{
    __shared__ float sv[NCHUNK * 9];   // [q][9] padding: stride 9 coprime to 32

    const int head = blockIdx.x;
    const int c0   = blockIdx.y * SCAN_G;
    const bool doB = (blockIdx.z == 0);
    float* __restrict__ cs =
        (doB ? ((L == 0) ? S.csB : S.csB2) : ((L == 0) ? S.csA : S.csA2))
        + (size_t)head * NCHUNK * C;

    const int t    = threadIdx.x;
    const int lane = t & 31;
    const int w    = t >> 5;           // warp id = local channel

    for (int idx = t; idx < NCHUNK * SCAN_G; idx += 256) {
        const int q  = idx >> 3;
        const int cl = idx & 7;
        sv[q * 9 + cl] = cs[q * C + c0 + cl];
    }
    __syncthreads();

    constexpr int R = NCHUNK / 32;     // 16 rounds per lane
    float vals[R], inc[R];
    #pragma unroll
    for (int i = 0; i < R; i++) {
        vals[i] = sv[(lane + 32 * i) * 9 + w];
        inc[i]  = vals[i];
    }

    #pragma unroll
    for (int d = 1; d < 32; d <<= 1) {
        #pragma unroll
        for (int i = 0; i < R; i++) {
            const float tv = __shfl_up_sync(0xffffffffu, inc[i], d);
            if (lane >= d) inc[i] += tv;
        }
    }
    float tot[R];
    #pragma unroll
    for (int i = 0; i < R; i++) tot[i] = __shfl_sync(0xffffffffu, inc[i], 31);

    if (doB) {
        float run = 0.f;
        #pragma unroll
        for (int i = 0; i < R; i++) {
            sv[(lane + 32 * i) * 9 + w] = run + (inc[i] - vals[i]);
            run += tot[i];
        }
    } else {
        float run = 0.f;
        #pragma unroll
        for (int i = R - 1; i >= 0; i--) {
            sv[(lane + 32 * i) * 9 + w] = run + (tot[i] - inc[i]);
            run += tot[i];
        }
    }
    __syncthreads();

    for (int idx = t; idx < NCHUNK * SCAN_G; idx += 256) {
        const int q  = idx >> 3;
        const int cl = idx & 7;
        cs[q * C + c0 + cl] = sv[q * 9 + cl];
    }
}

// ---------------------------------------------------------------------------
// Kernel 6: per-row combine. Row leader (c==0) precomputes folded coefficients
// coef_e = (p>=k ? ea*A_p : eb*B_p) and row offsets; workers do pure FMA+loads.
// block 256 = IPB rows x C channels.
// ---------------------------------------------------------------------------
template<int C, bool DO_ELU, int L>
__global__ void k_combine(float* __restrict__ extOut, int rowStride)
{
    constexpr int IPB = 256 / C;
    __shared__ float  sEa[IPB], sEb[IPB], sWii[IPB];
    __shared__ double sRd[IPB];
    __shared__ float  sCoef[IPB][CHSZ];
    __shared__ int    sOff[IPB][CHSZ];
    __shared__ int    sQ[IPB];

    const int head = blockIdx.y;
    const float*  __restrict__ s1     = ((L == 0) ? S.s1     : S.s1o)  + head * NN;
    const float*  __restrict__ s2     = ((L == 0) ? S.s2     : S.s2o)  + head * NN;
    const float*  __restrict__ s2s    = ((L == 0) ? S.s2s    : S.s2so) + head * NN;
    const int*    __restrict__ perm   = ((L == 0) ? S.perm   : S.permo) + head * NN;
    const float*  __restrict__ A      = ((L == 0) ? S.A      : S.Ao)   + head * NN;
    const float*  __restrict__ B      = ((L == 0) ? S.B      : S.Bo)   + head * NN;
    const float*  __restrict__ Wh     = ((L == 0) ? S.Wh     : S.Wh2)  + (size_t)head * NN * C;
    const float*  __restrict__ csAs   = ((L == 0) ? S.csA    : S.csA2) + (size_t)head * NCHUNK * C;
    const float*  __restrict__ csBs   = ((L == 0) ? S.csB    : S.csB2) + (size_t)head * NCHUNK * C;
    const double* __restrict__ sufAsc = ((L == 0) ? S.sufAsc : S.sufA2sc) + head * (NN + 1);
    const double* __restrict__ preBsc = ((L == 0) ? S.preBsc : S.preB2sc) + head * (NN + 1);
    float* __restrict__ out = (L == 0) ? S.hcat : extOut;

    const int r = threadIdx.x / C;
    const int i = blockIdx.x * IPB + r;
    const int c = threadIdx.x % C;

    if (c == 0) {
        const float s1v = s1[i];
        const float ea  = expf(s1v);
        const float eb  = expf(0.01f * s1v);
        const float target = -s1v;
        int lo = 0, hi = NN;
        while (lo < hi) {
            const int mid = (lo + hi) >> 1;
            if (s2s[mid] < target) lo = mid + 1; else hi = mid;
        }
        const int k = lo;
        const int q = min(k >> CHLOG, NCHUNK - 1);
        const int p0 = q << CHLOG;
        #pragma unroll
        for (int e = 0; e < CHSZ; e++) {
            const int p = p0 + e;
            sCoef[r][e] = (p >= k) ? ea * A[p] : eb * B[p];
            sOff[r][e]  = perm[p] * C;
        }
        const float tii = s1v + s2[i];
        const float wii = expf(tii >= 0.f ? tii : 0.01f * tii);
        const double denom = (double)ea * sufAsc[k] + (double)eb * preBsc[k] - (double)wii;
        sEa[r] = ea;  sEb[r] = eb;  sWii[r] = wii;  sQ[r] = q;
        sRd[r] = 1.0 / denom;
    }
    __syncthreads();

    const float  ea  = sEa[r];
    const float  eb  = sEb[r];
    const float  wii = sWii[r];
    const double rd  = sRd[r];
    const int    q   = sQ[r];

    // seeds from scanned chunk offsets (fold ea/eb here)
    float acc = ea * csAs[q * C + c] + eb * csBs[q * C + c];

    #pragma unroll
    for (int e = 0; e < CHSZ; e++)
        acc = fmaf(sCoef[r][e], Wh[(size_t)sOff[r][e] + c], acc);

    const float num = acc - wii * Wh[(size_t)i * C + c];
    float v = (float)((double)num * rd);
    if (DO_ELU) v = (v > 0.f) ? v : expm1f(v);

    out[(size_t)i * rowStride + head * C + c] = v;
}

// ---------------------------------------------------------------------------
// launch — kernel launches only (10 launches)
// ---------------------------------------------------------------------------
extern "C" void kernel_launch(void* const* d_in, const int* in_sizes, int n_in,
                              void* d_out, int out_size)
{
    const float* x       = (const float*)d_in[0];
    const float* W_heads = (const float*)d_in[3];
    const float* a1h     = (const float*)d_in[4];
    const float* a2h     = (const float*)d_in[5];
    const float* W_out   = (const float*)d_in[6];
    const float* a1o     = (const float*)d_in[7];
    const float* a2o     = (const float*)d_in[8];
    float* out = (float*)d_out;

    // ---- layer 1 (4 heads) ----
    k_gemm1<<<dim3(NN / 64, NH), 256>>>(x, W_heads, a1h, a2h);
    k_sortscan<0><<<NH, 1024>>>();
    k_chunksum<HIDC, 4, 0><<<dim3(NH, NCHUNK / 4), 256>>>();
    k_chunkscan<HIDC, 0><<<dim3(NH, HIDC / SCAN_G, 2), 256>>>();
    k_combine<HIDC, true, 0><<<dim3(NN / 4, NH), 256>>>(nullptr, NH * HIDC);

    // ---- layer 2 (output) ----
    k_gemm2<<<NN / 16, 256>>>(W_out, a1o, a2o);
    k_sortscan<1><<<1, 1024>>>();
    k_chunksum<TT, 16, 1><<<dim3(1, NCHUNK / 16), 256>>>();
    k_chunkscan<TT, 1><<<dim3(1, TT / SCAN_G, 2), 256>>>();
    k_combine<TT, false, 1><<<dim3(NN / 16, 1), 256>>>(out, TT);
}